// round 8
// baseline (speedup 1.0000x reference)
#include <cuda_runtime.h>

// out[b,i,n] = sum_j w[i,j] * x[b,j,n]
// x: [256, 3, 65536] fp32, w: [3,3] fp32, out: [256, 3, 65536] fp32
//
// DRAM mixed-stream limited (402.6 MB compulsory / period). v4: maximize
// memory-controller burst grouping: 12 front-batched independent LDG.128
// per thread, then 12 back-to-back STG.128. Default cache policy (best
// measured DRAM% across rounds).

static constexpr int N_COLS  = 65536;
static constexpr int N4      = N_COLS / 4;        // 16384 float4 per row
static constexpr int BATCH   = 256;
static constexpr long TOTAL4 = (long)BATCH * N4;  // 4,194,304
static constexpr int TPB     = 256;
static constexpr int VPT     = 4;                 // float4 positions per thread
static constexpr int PER_BLK = TPB * VPT;         // 1024 (divides 16384)

__global__ __launch_bounds__(TPB) void rot3_kernel_v4(
    const float4* __restrict__ x,
    const float*  __restrict__ w,
    float4* __restrict__ out)
{
    long base = (long)blockIdx.x * PER_BLK + threadIdx.x;
    int b  = (int)(base >> 14);        // base / N4  (same for whole block)
    int n0 = (int)(base & (N4 - 1));   // base % N4

    float w00 = __ldg(w + 0), w01 = __ldg(w + 1), w02 = __ldg(w + 2);
    float w10 = __ldg(w + 3), w11 = __ldg(w + 4), w12 = __ldg(w + 5);
    float w20 = __ldg(w + 6), w21 = __ldg(w + 7), w22 = __ldg(w + 8);

    const float4* xb = x + (size_t)b * 3 * N4;
    float4* ob = out + (size_t)b * 3 * N4;

    // ---- 12 independent front-batched loads (4 positions x 3 rows) ----
    float4 r0[VPT], r1[VPT], r2[VPT];
#pragma unroll
    for (int v = 0; v < VPT; v++) {
        int n = n0 + v * TPB;
        r0[v] = __ldg(xb + n);
        r1[v] = __ldg(xb + N4 + n);
        r2[v] = __ldg(xb + 2 * N4 + n);
    }

    // ---- compute all 12 outputs ----
    float4 s0[VPT], s1[VPT], s2[VPT];
#pragma unroll
    for (int v = 0; v < VPT; v++) {
        s0[v].x = w00*r0[v].x + w01*r1[v].x + w02*r2[v].x;
        s0[v].y = w00*r0[v].y + w01*r1[v].y + w02*r2[v].y;
        s0[v].z = w00*r0[v].z + w01*r1[v].z + w02*r2[v].z;
        s0[v].w = w00*r0[v].w + w01*r1[v].w + w02*r2[v].w;

        s1[v].x = w10*r0[v].x + w11*r1[v].x + w12*r2[v].x;
        s1[v].y = w10*r0[v].y + w11*r1[v].y + w12*r2[v].y;
        s1[v].z = w10*r0[v].z + w11*r1[v].z + w12*r2[v].z;
        s1[v].w = w10*r0[v].w + w11*r1[v].w + w12*r2[v].w;

        s2[v].x = w20*r0[v].x + w21*r1[v].x + w22*r2[v].x;
        s2[v].y = w20*r0[v].y + w21*r1[v].y + w22*r2[v].y;
        s2[v].z = w20*r0[v].z + w21*r1[v].z + w22*r2[v].z;
        s2[v].w = w20*r0[v].w + w21*r1[v].w + w22*r2[v].w;
    }

    // ---- 12 back-to-back stores ----
#pragma unroll
    for (int v = 0; v < VPT; v++) {
        int n = n0 + v * TPB;
        ob[n]          = s0[v];
        ob[N4 + n]     = s1[v];
        ob[2 * N4 + n] = s2[v];
    }
}

extern "C" void kernel_launch(void* const* d_in, const int* in_sizes, int n_in,
                              void* d_out, int out_size)
{
    const float4* x = (const float4*)d_in[0];
    const float*  w = (const float*)d_in[1];
    float4* out = (float4*)d_out;

    const long blocks = TOTAL4 / PER_BLK;  // 4096
    rot3_kernel_v4<<<(int)blocks, TPB>>>(x, w, out);
}

// round 10
// speedup vs baseline: 1.0116x; 1.0116x over previous
#include <cuda_runtime.h>

// out[b,i,n] = sum_j w[i,j] * x[b,j,n]
// x: [256, 3, 65536] fp32, w: [3,3] fp32, out: [256, 3, 65536] fp32
//
// v5: R1 structure (best measured DRAM%: default-policy loads, 1 float4/thread)
// with WRITE-THROUGH stores (__stwt). Rationale: steady-state replay period
// (63.55us) exceeds the ncu kernel window (55.2us) by ~8.4us — consistent with
// a dirty-L2 writeback drain at the replay boundary. Write-through lands the
// 192 MiB of store traffic in DRAM *during* the kernel, interleaved with the
// read stream, leaving no dirty tail to serialize the next replay.

static constexpr int N_COLS   = 65536;
static constexpr int N4       = N_COLS / 4;   // 16384 float4 per row
static constexpr int BATCH    = 256;
static constexpr long TOTAL4  = (long)BATCH * N4;  // 4,194,304 threads

__global__ __launch_bounds__(256) void rot3_kernel_v5(
    const float4* __restrict__ x,
    const float*  __restrict__ w,
    float4* __restrict__ out)
{
    long idx = (long)blockIdx.x * blockDim.x + threadIdx.x;
    if (idx >= TOTAL4) return;

    int b = (int)(idx >> 14);        // idx / N4
    int n = (int)(idx & (N4 - 1));   // idx % N4

    // Broadcast weight loads — L1-resident after first warp.
    float w00 = __ldg(w + 0), w01 = __ldg(w + 1), w02 = __ldg(w + 2);
    float w10 = __ldg(w + 3), w11 = __ldg(w + 4), w12 = __ldg(w + 5);
    float w20 = __ldg(w + 6), w21 = __ldg(w + 7), w22 = __ldg(w + 8);

    const float4* xb = x + (size_t)b * 3 * N4;
    float4 x0 = __ldg(xb + n);
    float4 x1 = __ldg(xb + N4 + n);
    float4 x2 = __ldg(xb + 2 * N4 + n);

    float4 o0, o1, o2;
    o0.x = w00 * x0.x + w01 * x1.x + w02 * x2.x;
    o0.y = w00 * x0.y + w01 * x1.y + w02 * x2.y;
    o0.z = w00 * x0.z + w01 * x1.z + w02 * x2.z;
    o0.w = w00 * x0.w + w01 * x1.w + w02 * x2.w;

    o1.x = w10 * x0.x + w11 * x1.x + w12 * x2.x;
    o1.y = w10 * x0.y + w11 * x1.y + w12 * x2.y;
    o1.z = w10 * x0.z + w11 * x1.z + w12 * x2.z;
    o1.w = w10 * x0.w + w11 * x1.w + w12 * x2.w;

    o2.x = w20 * x0.x + w21 * x1.x + w22 * x2.x;
    o2.y = w20 * x0.y + w21 * x1.y + w22 * x2.y;
    o2.z = w20 * x0.z + w21 * x1.z + w22 * x2.z;
    o2.w = w20 * x0.w + w21 * x1.w + w22 * x2.w;

    float4* ob = out + (size_t)b * 3 * N4;
    // Write-through: land stores in DRAM during the kernel window so the
    // replay boundary carries no dirty-L2 drain.
    __stwt(ob + n,          o0);
    __stwt(ob + N4 + n,     o1);
    __stwt(ob + 2 * N4 + n, o2);
}

extern "C" void kernel_launch(void* const* d_in, const int* in_sizes, int n_in,
                              void* d_out, int out_size)
{
    const float4* x = (const float4*)d_in[0];
    const float*  w = (const float*)d_in[1];
    float4* out = (float4*)d_out;

    const int threads = 256;
    const long blocks = (TOTAL4 + threads - 1) / threads;  // 16384
    rot3_kernel_v5<<<(int)blocks, threads>>>(x, w, out);
}